// round 15
// baseline (speedup 1.0000x reference)
#include <cuda_runtime.h>
#include <cuda_fp16.h>
#include <mma.h>

using namespace nvcuda;

// Problem constants
#define B_SZ   64
#define C_CH   256
#define HP     28
#define HW     784            // 28*28
#define NPIX   50176          // 64*784
#define MF     576            // 64 head-dims * 9 conv taps
#define KD     256

// ------------------------- device scratch -------------------------
__device__ __align__(256) __half g_Wf[MF * KD];          // folded fc_w x {w1,w2,w3}  (fp16)
__device__ float  g_bf[MF];                              // folded bias
__device__ __align__(256) __half g_xh[KD * NPIX];        // x as fp16 B-matrix [c][b*784+p]
__device__ __align__(256) __half g_f [MF * NPIX];        // f_conv (no bias) [ch][b*784+p]
__device__ float  g_xsum[B_SZ * C_CH * 25];              // 12x12 window sums of x (interior windows)
__device__ float  g_att [B_SZ * C_CH * 25];              // out_att value per interior window

// ------------------------- prep: fold weights -------------------------
// Wf[g*9+o][c] = sum_h fc[o][h]*w1[h*64+g][c] + fc[o][4+h]*w2[...] + fc[o][8+h]*w3[...]
__global__ void prep_kernel(const float* __restrict__ w1, const float* __restrict__ b1,
                            const float* __restrict__ w2, const float* __restrict__ b2,
                            const float* __restrict__ w3, const float* __restrict__ b3,
                            const float* __restrict__ fcw)
{
    int m = blockIdx.x;          // 0..575
    int g = m / 9, o = m % 9;
    int c = threadIdx.x;         // 0..255
    float s = 0.f;
#pragma unroll
    for (int h = 0; h < 4; ++h) {
        int ch = h * 64 + g;
        s += fcw[o * 12 + h]     * w1[ch * 256 + c];
        s += fcw[o * 12 + 4 + h] * w2[ch * 256 + c];
        s += fcw[o * 12 + 8 + h] * w3[ch * 256 + c];
    }
    g_Wf[m * 256 + c] = __float2half(s);
    if (c == 0) {
        float t = 0.f;
#pragma unroll
        for (int h = 0; h < 4; ++h) {
            int ch = h * 64 + g;
            t += fcw[o * 12 + h]     * b1[ch];
            t += fcw[o * 12 + 4 + h] * b2[ch];
            t += fcw[o * 12 + 8 + h] * b3[ch];
        }
        g_bf[m] = t;
    }
}

// ------------------------- pre_x: fp16 convert + separable window sums -------------------------
__global__ void pre_x_kernel(const float* __restrict__ x)
{
    int bc = blockIdx.x;                 // b*256 + c
    int b = bc >> 8, c = bc & 255;
    __shared__ float xs[784];
    __shared__ float rs[140];            // rowsum[y][j], j = window col idx 0..4 (interior)
    const float* src = x + (size_t)bc * 784;
    __half* dst = g_xh + (size_t)c * NPIX + b * 784;
    for (int i = threadIdx.x; i < 784; i += 256) {
        float v = src[i];
        xs[i] = v;
        dst[i] = __float2half(v);
    }
    __syncthreads();
    int t = threadIdx.x;
    if (t < 140) {
        int y = t / 5, j = t % 5, s0 = 4 * j;   // window j+1 covers cols 4j..4j+11
        const float* r = xs + y * 28 + s0;
        float a = 0.f;
#pragma unroll
        for (int u = 0; u < 12; ++u) a += r[u];
        rs[t] = a;
    }
    __syncthreads();
    if (t < 25) {
        int i = t / 5, j = t % 5, s0 = 4 * i;
        float a = 0.f;
#pragma unroll
        for (int u = 0; u < 12; ++u) a += rs[(s0 + u) * 5 + j];
        g_xsum[bc * 25 + t] = a;
    }
}

// ------------------------- attention branch: tiny GEMM W3 @ xmean + b3 -------------------------
__global__ void att_gemm_kernel(const float* __restrict__ w3, const float* __restrict__ b3)
{
    int b = blockIdx.x;                  // 0..63
    int oc = threadIdx.x;                // 0..255
    __shared__ float xs[256 * 25];
    for (int i = threadIdx.x; i < 6400; i += 256) xs[i] = g_xsum[b * 6400 + i];
    __syncthreads();
    float acc[25];
#pragma unroll
    for (int t = 0; t < 25; ++t) acc[t] = 0.f;
    const float4* w4 = (const float4*)(w3 + oc * 256);
    for (int cb = 0; cb < 64; ++cb) {
        float4 wv = __ldg(w4 + cb);
        const float* x0 = xs + (cb * 4) * 25;
#pragma unroll
        for (int t = 0; t < 25; ++t)
            acc[t] += wv.x * x0[t] + wv.y * x0[25 + t] + wv.z * x0[50 + t] + wv.w * x0[75 + t];
    }
    float bias = b3[oc];
    const float inv = 1.0f / 144.0f;
#pragma unroll
    for (int t = 0; t < 25; ++t)
        g_att[(b * 256 + oc) * 25 + t] = acc[t] * inv + bias;
}

// ------------------------- main GEMM: f = Wf(576x256) @ xh(256x50176), fp16 wmma -------------------------
__device__ __forceinline__ void cp16(void* sm, const void* gm)
{
    unsigned sa = (unsigned)__cvta_generic_to_shared(sm);
    asm volatile("cp.async.cg.shared.global [%0], [%1], 16;\n" :: "r"(sa), "l"(gm));
}

__global__ void __launch_bounds__(256) gemm_f_kernel()
{
    extern __shared__ __align__(16) unsigned char dynsm[];
    __half* As = (__half*)dynsm;                       // [2][64*40]
    __half* Bs = (__half*)(dynsm + 2 * 64 * 40 * 2);   // [2][32*136]
    float*  Cs = (float*)dynsm;                        // epilogue reuse: 8 warps * 1024 floats

    const int t  = threadIdx.x;
    const int m0 = blockIdx.x * 64;     // gridDim.x = 9
    const int n0 = blockIdx.y * 128;    // gridDim.y = 392

    const int ar = t >> 2, ac = (t & 3) * 8;
    const int br = t >> 3, bc = (t & 7) * 16;
    const __half* Ag = g_Wf + (m0 + ar) * 256 + ac;
    const __half* Bg = g_xh + br * NPIX + n0 + bc;

    auto ld = [&](int kt, int st) {
        cp16(As + st * 2560 + ar * 40 + ac, Ag + kt * 32);
        const __half* s = Bg + kt * 32 * NPIX;
        cp16(Bs + st * 4352 + br * 136 + bc,     s);
        cp16(Bs + st * 4352 + br * 136 + bc + 8, s + 8);
        asm volatile("cp.async.commit_group;\n");
    };
    ld(0, 0);
    ld(1, 1);
    asm volatile("cp.async.wait_group 1;\n");
    __syncthreads();

    const int warp = t >> 5;
    const int row0 = (warp >> 2) * 32;  // 2 warp-rows
    const int col0 = (warp & 3) * 32;   // 4 warp-cols

    wmma::fragment<wmma::matrix_a, 16, 16, 16, __half, wmma::row_major> fa[2];
    wmma::fragment<wmma::matrix_b, 16, 16, 16, __half, wmma::row_major> fb[2];
    wmma::fragment<wmma::accumulator, 16, 16, 16, float> fc[2][2];
#pragma unroll
    for (int i = 0; i < 2; ++i)
#pragma unroll
        for (int j = 0; j < 2; ++j) wmma::fill_fragment(fc[i][j], 0.f);

#pragma unroll 1
    for (int kt = 0; kt < 8; ++kt) {
        int cur = kt & 1;
        const __half* Ab = As + cur * 2560;
        const __half* Bb = Bs + cur * 4352;
#pragma unroll
        for (int ks = 0; ks < 2; ++ks) {
            wmma::load_matrix_sync(fa[0], Ab + row0 * 40 + ks * 16, 40);
            wmma::load_matrix_sync(fa[1], Ab + (row0 + 16) * 40 + ks * 16, 40);
            wmma::load_matrix_sync(fb[0], Bb + ks * 16 * 136 + col0, 136);
            wmma::load_matrix_sync(fb[1], Bb + ks * 16 * 136 + col0 + 16, 136);
#pragma unroll
            for (int i = 0; i < 2; ++i)
#pragma unroll
                for (int j = 0; j < 2; ++j)
                    wmma::mma_sync(fc[i][j], fa[i], fb[j], fc[i][j]);
        }
        if (kt + 2 < 8) {
            __syncthreads();
            ld(kt + 2, cur);
            asm volatile("cp.async.wait_group 1;\n");
            __syncthreads();
        } else if (kt + 1 < 8) {
            asm volatile("cp.async.wait_group 0;\n");
            __syncthreads();
        }
    }
    __syncthreads();

    // epilogue: frags -> smem fp32 -> fp16 global (no bias: handled in final kernel)
#pragma unroll
    for (int i = 0; i < 2; ++i)
#pragma unroll
        for (int j = 0; j < 2; ++j)
            wmma::store_matrix_sync(Cs + warp * 1024 + i * 512 + j * 16, fc[i][j], 32, wmma::mem_row_major);
    __syncthreads();

#pragma unroll
    for (int it = 0; it < 4; ++it) {
        int idx = it * 2048 + t * 8;
        int row = idx >> 7, col = idx & 127;
        int wreg = (row >> 5) * 4 + (col >> 5);
        const float* src = Cs + wreg * 1024 + (row & 31) * 32 + (col & 31);
        __half h[8];
#pragma unroll
        for (int u = 0; u < 8; ++u) h[u] = __float2half(src[u]);
        *(uint4*)(g_f + (size_t)(m0 + row) * NPIX + n0 + col) = *(uint4*)h;
    }
}

// ------------------------- final: grouped 3x3 conv + att broadcast + combine -------------------------
__global__ void __launch_bounds__(256) final_kernel(const float* __restrict__ dep_w,
                                                    const float* __restrict__ rate1,
                                                    const float* __restrict__ rate2,
                                                    float* __restrict__ out)
{
    int g = blockIdx.x;   // head-dim group 0..63
    int b = blockIdx.y;   // batch 0..63
    __shared__ float fs[9 * 784];
    __shared__ float ws[324];      // dep_w slice: [r(4)][o(9)][tap(9)]
    __shared__ float bc9[36];      // per-(r,tap) bias contribution
    __shared__ float atts[100];    // [r(4)][25 interior windows]
    __shared__ float bf9s[9];

    int t = threadIdx.x;
#pragma unroll
    for (int o = 0; o < 9; ++o)
        for (int i = t; i < 784; i += 256)
            fs[o * 784 + i] = __half2float(g_f[(size_t)(g * 9 + o) * NPIX + b * 784 + i]);
    for (int i = t; i < 324; i += 256) ws[i] = dep_w[g * 4 * 81 + i];
    if (t < 100) atts[t] = g_att[(b * 256 + 4 * g) * 25 + t];
    if (t < 9)   bf9s[t] = g_bf[g * 9 + t];
    __syncthreads();
    if (t < 36) {
        int r = t / 9, tap = t % 9;
        float s = 0.f;
#pragma unroll
        for (int o = 0; o < 9; ++o) s += ws[r * 81 + o * 9 + tap] * bf9s[o];
        bc9[t] = s;
    }
    __syncthreads();

    float r1 = *rate1, r2 = *rate2;

    for (int p = t; p < 784; p += 256) {
        int y = p / 28, x = p - y * 28;
        float a0 = 0.f, a1 = 0.f, a2 = 0.f, a3 = 0.f;
#pragma unroll
        for (int ky = 0; ky < 3; ++ky) {
            int yy = y + ky - 1;
            if ((unsigned)yy > 27u) continue;
            int rb = yy * 28;
#pragma unroll
            for (int kx = 0; kx < 3; ++kx) {
                int xx = x + kx - 1;
                if ((unsigned)xx > 27u) continue;
                int tap = ky * 3 + kx;
                int fi = rb + xx;
#pragma unroll
                for (int o = 0; o < 9; ++o) {
                    float v = fs[o * 784 + fi];
                    a0 += v * ws[        o * 9 + tap];
                    a1 += v * ws[ 81 +   o * 9 + tap];
                    a2 += v * ws[162 +   o * 9 + tap];
                    a3 += v * ws[243 +   o * 9 + tap];
                }
                a0 += bc9[tap];
                a1 += bc9[9  + tap];
                a2 += bc9[18 + tap];
                a3 += bc9[27 + tap];
            }
        }
        // attention branch: uniform window mean for interior blocks, else 0
        float t0 = 0.f, t1 = 0.f, t2 = 0.f, t3 = 0.f;
        int iy = y >> 2, jx = x >> 2;
        if (iy >= 1 && iy <= 5 && jx >= 1 && jx <= 5) {
            int w = (iy - 1) * 5 + (jx - 1);
            t0 = atts[w]; t1 = atts[25 + w]; t2 = atts[50 + w]; t3 = atts[75 + w];
        }
        int ob = (b * 256 + 4 * g) * 784 + p;
        out[ob]           = r1 * t0 + r2 * a0;
        out[ob + 784]     = r1 * t1 + r2 * a1;
        out[ob + 2 * 784] = r1 * t2 + r2 * a2;
        out[ob + 3 * 784] = r1 * t3 + r2 * a3;
    }
}

// ------------------------- launch -------------------------
extern "C" void kernel_launch(void* const* d_in, const int* in_sizes, int n_in,
                              void* d_out, int out_size)
{
    const float* x    = (const float*)d_in[0];
    const float* w1   = (const float*)d_in[1];
    const float* b1   = (const float*)d_in[2];
    const float* w2   = (const float*)d_in[3];
    const float* b2   = (const float*)d_in[4];
    const float* w3   = (const float*)d_in[5];
    const float* b3   = (const float*)d_in[6];
    const float* fcw  = (const float*)d_in[7];
    const float* depw = (const float*)d_in[8];
    // d_in[9], d_in[10]: rel_height / rel_width — mathematically dead (inverted mask)
    const float* rate1 = (const float*)d_in[11];
    const float* rate2 = (const float*)d_in[12];
    float* out = (float*)d_out;

    prep_kernel<<<MF, 256>>>(w1, b1, w2, b2, w3, b3, fcw);
    pre_x_kernel<<<B_SZ * C_CH, 256>>>(x);
    att_gemm_kernel<<<B_SZ, 256>>>(w3, b3);
    gemm_f_kernel<<<dim3(9, 392), 256, 32768>>>();
    final_kernel<<<dim3(64, B_SZ), 256>>>(depw, rate1, rate2, out);
}

// round 16
// speedup vs baseline: 1.0120x; 1.0120x over previous
#include <cuda_runtime.h>
#include <cuda_fp16.h>
#include <mma.h>

using namespace nvcuda;

// Problem constants
#define B_SZ   64
#define C_CH   256
#define HP     28
#define HW     784            // 28*28
#define NPIX   50176          // 64*784
#define MF     576            // 64 head-dims * 9 conv taps
#define KD     256

// ------------------------- device scratch -------------------------
__device__ __align__(256) __half g_Wf[MF * KD];          // folded fc_w x {w1,w2,w3}  (fp16)
__device__ float  g_bf[MF];                              // folded bias
__device__ __align__(256) __half g_xh[KD * NPIX];        // x as fp16 B-matrix [c][b*784+p]
__device__ __align__(256) __half g_f [MF * NPIX];        // f_conv (no bias) [ch][b*784+p]
__device__ float  g_xsum[B_SZ * C_CH * 25];              // 12x12 window sums of x (interior windows)
__device__ float  g_att [B_SZ * C_CH * 25];              // out_att value per interior window

// ------------------------- prep: fold weights -------------------------
// Wf[g*9+o][c] = sum_h fc[o][h]*w1[h*64+g][c] + fc[o][4+h]*w2[...] + fc[o][8+h]*w3[...]
__global__ void prep_kernel(const float* __restrict__ w1, const float* __restrict__ b1,
                            const float* __restrict__ w2, const float* __restrict__ b2,
                            const float* __restrict__ w3, const float* __restrict__ b3,
                            const float* __restrict__ fcw)
{
    int m = blockIdx.x;          // 0..575
    int g = m / 9, o = m % 9;
    int c = threadIdx.x;         // 0..255
    float s = 0.f;
#pragma unroll
    for (int h = 0; h < 4; ++h) {
        int ch = h * 64 + g;
        s += fcw[o * 12 + h]     * w1[ch * 256 + c];
        s += fcw[o * 12 + 4 + h] * w2[ch * 256 + c];
        s += fcw[o * 12 + 8 + h] * w3[ch * 256 + c];
    }
    g_Wf[m * 256 + c] = __float2half(s);
    if (c == 0) {
        float t = 0.f;
#pragma unroll
        for (int h = 0; h < 4; ++h) {
            int ch = h * 64 + g;
            t += fcw[o * 12 + h]     * b1[ch];
            t += fcw[o * 12 + 4 + h] * b2[ch];
            t += fcw[o * 12 + 8 + h] * b3[ch];
        }
        g_bf[m] = t;
    }
}

// ------------------------- pre_x: fp16 convert + separable window sums -------------------------
__global__ void pre_x_kernel(const float* __restrict__ x)
{
    int bc = blockIdx.x;                 // b*256 + c
    int b = bc >> 8, c = bc & 255;
    __shared__ float xs[784];
    __shared__ float rs[140];            // rowsum[y][j], j = window col idx 0..4 (interior)
    const float* src = x + (size_t)bc * 784;
    __half* dst = g_xh + (size_t)c * NPIX + b * 784;
    for (int i = threadIdx.x; i < 784; i += 256) {
        float v = src[i];
        xs[i] = v;
        dst[i] = __float2half(v);
    }
    __syncthreads();
    int t = threadIdx.x;
    if (t < 140) {
        int y = t / 5, j = t % 5, s0 = 4 * j;   // window j+1 covers cols 4j..4j+11
        const float* r = xs + y * 28 + s0;
        float a = 0.f;
#pragma unroll
        for (int u = 0; u < 12; ++u) a += r[u];
        rs[t] = a;
    }
    __syncthreads();
    if (t < 25) {
        int i = t / 5, j = t % 5, s0 = 4 * i;
        float a = 0.f;
#pragma unroll
        for (int u = 0; u < 12; ++u) a += rs[(s0 + u) * 5 + j];
        g_xsum[bc * 25 + t] = a;
    }
}

// ------------------------- attention branch: tiny GEMM W3 @ xmean + b3 -------------------------
__global__ void att_gemm_kernel(const float* __restrict__ w3, const float* __restrict__ b3)
{
    int b = blockIdx.x;                  // 0..63
    int oc = threadIdx.x;                // 0..255
    __shared__ float xs[256 * 25];
    for (int i = threadIdx.x; i < 6400; i += 256) xs[i] = g_xsum[b * 6400 + i];
    __syncthreads();
    float acc[25];
#pragma unroll
    for (int t = 0; t < 25; ++t) acc[t] = 0.f;
    const float4* w4 = (const float4*)(w3 + oc * 256);
    for (int cb = 0; cb < 64; ++cb) {
        float4 wv = __ldg(w4 + cb);
        const float* x0 = xs + (cb * 4) * 25;
#pragma unroll
        for (int t = 0; t < 25; ++t)
            acc[t] += wv.x * x0[t] + wv.y * x0[25 + t] + wv.z * x0[50 + t] + wv.w * x0[75 + t];
    }
    float bias = b3[oc];
    const float inv = 1.0f / 144.0f;
#pragma unroll
    for (int t = 0; t < 25; ++t)
        g_att[(b * 256 + oc) * 25 + t] = acc[t] * inv + bias;
}

// ------------------------- main GEMM: f = Wf(576x256) @ xh(256x50176), fp16 wmma -------------------------
__device__ __forceinline__ void cp16(void* sm, const void* gm)
{
    unsigned sa = (unsigned)__cvta_generic_to_shared(sm);
    asm volatile("cp.async.cg.shared.global [%0], [%1], 16;\n" :: "r"(sa), "l"(gm));
}

__global__ void __launch_bounds__(256) gemm_f_kernel()
{
    extern __shared__ __align__(16) unsigned char dynsm[];
    __half* As = (__half*)dynsm;                       // [2][64*40]
    __half* Bs = (__half*)(dynsm + 2 * 64 * 40 * 2);   // [2][32*136]
    float*  Cs = (float*)dynsm;                        // epilogue reuse: 8 warps * 1024 floats

    const int t  = threadIdx.x;
    const int m0 = blockIdx.x * 64;     // gridDim.x = 9
    const int n0 = blockIdx.y * 128;    // gridDim.y = 392

    const int ar = t >> 2, ac = (t & 3) * 8;
    const int br = t >> 3, bc = (t & 7) * 16;
    const __half* Ag = g_Wf + (m0 + ar) * 256 + ac;
    const __half* Bg = g_xh + br * NPIX + n0 + bc;

    auto ld = [&](int kt, int st) {
        cp16(As + st * 2560 + ar * 40 + ac, Ag + kt * 32);
        const __half* s = Bg + kt * 32 * NPIX;
        cp16(Bs + st * 4352 + br * 136 + bc,     s);
        cp16(Bs + st * 4352 + br * 136 + bc + 8, s + 8);
        asm volatile("cp.async.commit_group;\n");
    };
    ld(0, 0);
    ld(1, 1);
    asm volatile("cp.async.wait_group 1;\n");
    __syncthreads();

    const int warp = t >> 5;
    const int row0 = (warp >> 2) * 32;  // 2 warp-rows
    const int col0 = (warp & 3) * 32;   // 4 warp-cols

    wmma::fragment<wmma::matrix_a, 16, 16, 16, __half, wmma::row_major> fa[2];
    wmma::fragment<wmma::matrix_b, 16, 16, 16, __half, wmma::row_major> fb[2];
    wmma::fragment<wmma::accumulator, 16, 16, 16, float> fc[2][2];
#pragma unroll
    for (int i = 0; i < 2; ++i)
#pragma unroll
        for (int j = 0; j < 2; ++j) wmma::fill_fragment(fc[i][j], 0.f);

#pragma unroll 1
    for (int kt = 0; kt < 8; ++kt) {
        int cur = kt & 1;
        const __half* Ab = As + cur * 2560;
        const __half* Bb = Bs + cur * 4352;
#pragma unroll
        for (int ks = 0; ks < 2; ++ks) {
            wmma::load_matrix_sync(fa[0], Ab + row0 * 40 + ks * 16, 40);
            wmma::load_matrix_sync(fa[1], Ab + (row0 + 16) * 40 + ks * 16, 40);
            wmma::load_matrix_sync(fb[0], Bb + ks * 16 * 136 + col0, 136);
            wmma::load_matrix_sync(fb[1], Bb + ks * 16 * 136 + col0 + 16, 136);
#pragma unroll
            for (int i = 0; i < 2; ++i)
#pragma unroll
                for (int j = 0; j < 2; ++j)
                    wmma::mma_sync(fc[i][j], fa[i], fb[j], fc[i][j]);
        }
        if (kt + 2 < 8) {
            __syncthreads();
            ld(kt + 2, cur);
            asm volatile("cp.async.wait_group 1;\n");
            __syncthreads();
        } else if (kt + 1 < 8) {
            asm volatile("cp.async.wait_group 0;\n");
            __syncthreads();
        }
    }
    __syncthreads();

    // epilogue: frags -> smem fp32 -> fp16 global (no bias: handled in final kernel)
#pragma unroll
    for (int i = 0; i < 2; ++i)
#pragma unroll
        for (int j = 0; j < 2; ++j)
            wmma::store_matrix_sync(Cs + warp * 1024 + i * 512 + j * 16, fc[i][j], 32, wmma::mem_row_major);
    __syncthreads();

#pragma unroll
    for (int it = 0; it < 4; ++it) {
        int idx = it * 2048 + t * 8;
        int row = idx >> 7, col = idx & 127;
        int wreg = (row >> 5) * 4 + (col >> 5);
        const float* src = Cs + wreg * 1024 + (row & 31) * 32 + (col & 31);
        __half h[8];
#pragma unroll
        for (int u = 0; u < 8; ++u) h[u] = __float2half(src[u]);
        *(uint4*)(g_f + (size_t)(m0 + row) * NPIX + n0 + col) = *(uint4*)h;
    }
}

// ------------------------- final: grouped 3x3 conv + att broadcast + combine -------------------------
__global__ void __launch_bounds__(256) final_kernel(const float* __restrict__ dep_w,
                                                    const float* __restrict__ rate1,
                                                    const float* __restrict__ rate2,
                                                    float* __restrict__ out)
{
    int g = blockIdx.x;   // head-dim group 0..63
    int b = blockIdx.y;   // batch 0..63
    __shared__ float fs[9 * 784];
    __shared__ float ws[324];      // dep_w slice: [r(4)][o(9)][tap(9)]
    __shared__ float bc9[36];      // per-(r,tap) bias contribution
    __shared__ float atts[100];    // [r(4)][25 interior windows]
    __shared__ float bf9s[9];

    int t = threadIdx.x;
#pragma unroll
    for (int o = 0; o < 9; ++o)
        for (int i = t; i < 784; i += 256)
            fs[o * 784 + i] = __half2float(g_f[(size_t)(g * 9 + o) * NPIX + b * 784 + i]);
    for (int i = t; i < 324; i += 256) ws[i] = dep_w[g * 4 * 81 + i];
    if (t < 100) atts[t] = g_att[(b * 256 + 4 * g) * 25 + t];
    if (t < 9)   bf9s[t] = g_bf[g * 9 + t];
    __syncthreads();
    if (t < 36) {
        int r = t / 9, tap = t % 9;
        float s = 0.f;
#pragma unroll
        for (int o = 0; o < 9; ++o) s += ws[r * 81 + o * 9 + tap] * bf9s[o];
        bc9[t] = s;
    }
    __syncthreads();

    float r1 = *rate1, r2 = *rate2;

    for (int p = t; p < 784; p += 256) {
        int y = p / 28, x = p - y * 28;
        float a0 = 0.f, a1 = 0.f, a2 = 0.f, a3 = 0.f;
#pragma unroll
        for (int ky = 0; ky < 3; ++ky) {
            int yy = y + ky - 1;
            if ((unsigned)yy > 27u) continue;
            int rb = yy * 28;
#pragma unroll
            for (int kx = 0; kx < 3; ++kx) {
                int xx = x + kx - 1;
                if ((unsigned)xx > 27u) continue;
                int tap = ky * 3 + kx;
                int fi = rb + xx;
#pragma unroll
                for (int o = 0; o < 9; ++o) {
                    float v = fs[o * 784 + fi];
                    a0 += v * ws[        o * 9 + tap];
                    a1 += v * ws[ 81 +   o * 9 + tap];
                    a2 += v * ws[162 +   o * 9 + tap];
                    a3 += v * ws[243 +   o * 9 + tap];
                }
                a0 += bc9[tap];
                a1 += bc9[9  + tap];
                a2 += bc9[18 + tap];
                a3 += bc9[27 + tap];
            }
        }
        // attention branch: uniform window mean for interior blocks, else 0
        float t0 = 0.f, t1 = 0.f, t2 = 0.f, t3 = 0.f;
        int iy = y >> 2, jx = x >> 2;
        if (iy >= 1 && iy <= 5 && jx >= 1 && jx <= 5) {
            int w = (iy - 1) * 5 + (jx - 1);
            t0 = atts[w]; t1 = atts[25 + w]; t2 = atts[50 + w]; t3 = atts[75 + w];
        }
        int ob = (b * 256 + 4 * g) * 784 + p;
        out[ob]           = r1 * t0 + r2 * a0;
        out[ob + 784]     = r1 * t1 + r2 * a1;
        out[ob + 2 * 784] = r1 * t2 + r2 * a2;
        out[ob + 3 * 784] = r1 * t3 + r2 * a3;
    }
}

// ------------------------- launch -------------------------
extern "C" void kernel_launch(void* const* d_in, const int* in_sizes, int n_in,
                              void* d_out, int out_size)
{
    const float* x    = (const float*)d_in[0];
    const float* w1   = (const float*)d_in[1];
    const float* b1   = (const float*)d_in[2];
    const float* w2   = (const float*)d_in[3];
    const float* b2   = (const float*)d_in[4];
    const float* w3   = (const float*)d_in[5];
    const float* b3   = (const float*)d_in[6];
    const float* fcw  = (const float*)d_in[7];
    const float* depw = (const float*)d_in[8];
    // d_in[9], d_in[10]: rel_height / rel_width — mathematically dead (inverted mask)
    const float* rate1 = (const float*)d_in[11];
    const float* rate2 = (const float*)d_in[12];
    float* out = (float*)d_out;

    prep_kernel<<<MF, 256>>>(w1, b1, w2, b2, w3, b3, fcw);
    pre_x_kernel<<<B_SZ * C_CH, 256>>>(x);
    att_gemm_kernel<<<B_SZ, 256>>>(w3, b3);
    gemm_f_kernel<<<dim3(9, 392), 256, 32768>>>();
    final_kernel<<<dim3(64, B_SZ), 256>>>(depw, rate1, rate2, out);
}